// round 1
// baseline (speedup 1.0000x reference)
#include <cuda_runtime.h>

#define NUM_GRAPHS 2048
#define HID   200
#define EMB   200
#define DIN   400
#define H1    256
#define H2    64
#define TM    32          // nodes per block
#define NTHREADS 256

// segment-sum accumulator (scratch: __device__ global, no allocation)
__device__ float g_pool[NUM_GRAPHS * H2];

__global__ void zero_pool_kernel() {
    int i = blockIdx.x * blockDim.x + threadIdx.x;
    if (i < NUM_GRAPHS * H2) g_pool[i] = 0.0f;
}

// Fused: concat -> FC1(400->256)+ReLU -> FC2(256->64)+ReLU -> atomic segment add.
// Block = 256 threads = 64 col-threads x 4 node-groups; TM=32 nodes per block.
// Thread layout L1: cols [4*(t&63) .. +3], nodes [8*(t>>6) .. +7].
extern __shared__ float s[];   // max(TM*DIN, TM*H1) floats = 12800 -> 51.2 KB

__global__ __launch_bounds__(NTHREADS) void mlp_kernel(
    const float* __restrict__ h, const float* __restrict__ x,
    const int*   __restrict__ batch,
    const float* __restrict__ W1, const float* __restrict__ b1,
    const float* __restrict__ W2, const float* __restrict__ b2)
{
    const int t = threadIdx.x;
    const int node0 = blockIdx.x * TM;

    // ---- stage feat[m][k] = concat(h,x) into smem ----
    for (int idx = t; idx < TM * DIN; idx += NTHREADS) {
        int m = idx / DIN;
        int k = idx - m * DIN;
        float v = (k < HID) ? h[(size_t)(node0 + m) * HID + k]
                            : x[(size_t)(node0 + m) * EMB + (k - HID)];
        s[m * DIN + k] = v;
    }
    __syncthreads();

    // ---- layer 1: [TM,400] x [400,256] ----
    const int jc = (t & 63) * 4;   // output-col base
    const int mb = (t >> 6) * 8;   // node base within tile

    float acc[8][4];
    {
        float4 bb = *(const float4*)&b1[jc];
        #pragma unroll
        for (int m = 0; m < 8; m++) {
            acc[m][0] = bb.x; acc[m][1] = bb.y; acc[m][2] = bb.z; acc[m][3] = bb.w;
        }
    }
    const float* srow = &s[mb * DIN];
    #pragma unroll 2
    for (int k = 0; k < DIN; k++) {
        float4 w = *(const float4*)&W1[k * H1 + jc];
        #pragma unroll
        for (int m = 0; m < 8; m++) {
            float f = srow[m * DIN + k];
            acc[m][0] = fmaf(f, w.x, acc[m][0]);
            acc[m][1] = fmaf(f, w.y, acc[m][1]);
            acc[m][2] = fmaf(f, w.z, acc[m][2]);
            acc[m][3] = fmaf(f, w.w, acc[m][3]);
        }
    }
    __syncthreads();   // feat no longer needed; reuse smem for z1

    // write z1 = relu(acc) as [m][256]
    #pragma unroll
    for (int m = 0; m < 8; m++) {
        float4 z;
        z.x = fmaxf(acc[m][0], 0.0f);
        z.y = fmaxf(acc[m][1], 0.0f);
        z.z = fmaxf(acc[m][2], 0.0f);
        z.w = fmaxf(acc[m][3], 0.0f);
        *(float4*)&s[(mb + m) * H1 + jc] = z;
    }
    __syncthreads();

    // ---- layer 2: [TM,256] x [256,64] ----
    const int c = t & 63;           // output col 0..63
    float acc2[8];
    {
        float b2c = b2[c];
        #pragma unroll
        for (int m = 0; m < 8; m++) acc2[m] = b2c;
    }
    const float* zrow = &s[mb * H1];
    #pragma unroll 2
    for (int j = 0; j < H1; j++) {
        float w2 = W2[j * H2 + c];
        #pragma unroll
        for (int m = 0; m < 8; m++)
            acc2[m] = fmaf(zrow[m * H1 + j], w2, acc2[m]);
    }

    // ---- relu + run-merged segment atomics (batch is sorted) ----
    const int node = node0 + mb;
    int   cur = batch[node];
    float sum = fmaxf(acc2[0], 0.0f);
    #pragma unroll
    for (int m = 1; m < 8; m++) {
        int g = batch[node + m];
        float v = fmaxf(acc2[m], 0.0f);
        if (g == cur) {
            sum += v;
        } else {
            atomicAdd(&g_pool[cur * H2 + c], sum);
            cur = g; sum = v;
        }
    }
    atomicAdd(&g_pool[cur * H2 + c], sum);
}

// final: out[g] = sigmoid(pool[g,:] . Wout + bout) ; one warp per graph
__global__ void out_kernel(const float* __restrict__ Wout,
                           const float* __restrict__ bout,
                           float* __restrict__ out)
{
    int gw   = (blockIdx.x * blockDim.x + threadIdx.x) >> 5;
    int lane = threadIdx.x & 31;
    if (gw >= NUM_GRAPHS) return;
    float a = g_pool[gw * H2 + lane]      * Wout[lane]
            + g_pool[gw * H2 + 32 + lane] * Wout[32 + lane];
    #pragma unroll
    for (int o = 16; o; o >>= 1) a += __shfl_xor_sync(0xffffffffu, a, o);
    if (lane == 0) out[gw] = 1.0f / (1.0f + expf(-(a + bout[0])));
}

extern "C" void kernel_launch(void* const* d_in, const int* in_sizes, int n_in,
                              void* d_out, int out_size)
{
    const float* h    = (const float*)d_in[0];
    const float* x    = (const float*)d_in[1];
    const int*   batch= (const int*)  d_in[2];
    const float* W1   = (const float*)d_in[3];
    const float* b1   = (const float*)d_in[4];
    const float* W2   = (const float*)d_in[5];
    const float* b2   = (const float*)d_in[6];
    const float* Wout = (const float*)d_in[7];
    const float* bout = (const float*)d_in[8];
    float* out = (float*)d_out;

    const int N = in_sizes[2];            // 200000 nodes
    const int nblocks = N / TM;           // 200000/32 = 6250 exactly

    static int smem_set = -1;
    const int smem_bytes = TM * DIN * sizeof(float);   // 51200
    // idempotent attribute set (not a stream op; safe under capture)
    cudaFuncSetAttribute(mlp_kernel, cudaFuncAttributeMaxDynamicSharedMemorySize, smem_bytes);
    (void)smem_set;

    zero_pool_kernel<<<(NUM_GRAPHS * H2 + 255) / 256, 256>>>();
    mlp_kernel<<<nblocks, NTHREADS, smem_bytes>>>(h, x, batch, W1, b1, W2, b2);
    out_kernel<<<(NUM_GRAPHS * 32 + 255) / 256, 256>>>(Wout, bout, out);
}

// round 10
// speedup vs baseline: 3.1633x; 3.1633x over previous
#include <cuda_runtime.h>
#include <cstdint>

#define NG    2048
#define HID   200
#define DIN   400
#define KPAD  416
#define N1    256
#define H2    64
#define TM    128
#define NTH   512
#define NCHUNK 13

// -------- device scratch --------
__device__ float g_pool[NG * H2];
__device__ float g_w1t[N1 * KPAD];   // [n][k] K-major, tf32-rounded bits, zero-padded
__device__ float g_w2t[H2 * N1];     // [n][k] K-major, tf32-rounded bits

// -------- helpers --------
__device__ __forceinline__ uint32_t smem_u32(const void* p) {
    uint32_t a;
    asm("{ .reg .u64 t; cvta.to.shared.u64 t, %1; cvt.u32.u64 %0, t; }" : "=r"(a) : "l"(p));
    return a;
}
__device__ __forceinline__ uint32_t tf32b(float f) {
    uint32_t u; asm("cvt.rna.tf32.f32 %0, %1;" : "=r"(u) : "f"(f)); return u;
}
__device__ __forceinline__ void cp16(uint32_t dst, const void* src) {
    asm volatile("cp.async.cg.shared.global [%0], [%1], 16;" :: "r"(dst), "l"(src) : "memory");
}
#define CP_COMMIT asm volatile("cp.async.commit_group;" ::: "memory")
#define CP_WAIT1  asm volatile("cp.async.wait_group 1;" ::: "memory")
#define CP_WAIT0  asm volatile("cp.async.wait_group 0;" ::: "memory")

__device__ __forceinline__ void mma_tf32(float c[4], uint32_t a0, uint32_t a1, uint32_t a2, uint32_t a3,
                                         uint32_t b0, uint32_t b1) {
    asm volatile("mma.sync.aligned.m16n8k8.row.col.f32.tf32.tf32.f32 "
                 "{%0,%1,%2,%3},{%4,%5,%6,%7},{%8,%9},{%0,%1,%2,%3};"
                 : "+f"(c[0]), "+f"(c[1]), "+f"(c[2]), "+f"(c[3])
                 : "r"(a0), "r"(a1), "r"(a2), "r"(a3), "r"(b0), "r"(b1));
}

// chunk tiles: rows of 32 floats = 128B; 16B groups XOR-swizzled by row
__device__ __forceinline__ uint32_t adrC(int row, int k) {   // k in [0,32)
    return (uint32_t)(row * 128 + (((k >> 2) ^ (row & 7)) << 4) + (k & 3) * 4);
}
// wide tiles: rows of 256 floats = 1024B; swizzle within each 128B block
__device__ __forceinline__ uint32_t adrW(int row, int k) {   // k in [0,256)
    return (uint32_t)(row * 1024 + ((k >> 5) << 7) + ((((k >> 2) & 7) ^ (row & 7)) << 4) + (k & 3) * 4);
}

// -------- SMEM layout --------
#define OFF_B1   0           // 256 f
#define OFF_B2   1024        // 64 f
#define OFF_A    2048        // 3 x 16384
#define OFF_BB   51200       // 3 x 32768 (ends 149504)
#define OFF_Z1   2048        // 128 x 1024 = 131072 (reuses A/B bufs, ends 133120)
#define OFF_Z2   2048        // 128 x 68 x 4 = 34816 (reuses z1)
#define OFF_W2   149504      // 64 x 1024 = 65536 (ends 215040)
#define SMEM_BYTES 215040

// -------- prep: transpose + tf32-round weights --------
__global__ void prep_kernel(const float* __restrict__ W1, const float* __restrict__ W2) {
    int i = blockIdx.x * blockDim.x + threadIdx.x;
    const int T1 = N1 * KPAD;
    if (i < T1) {
        int n = i / KPAD, k = i - n * KPAD;
        g_w1t[i] = (k < DIN) ? __uint_as_float(tf32b(W1[k * N1 + n])) : 0.0f;
    } else {
        int j = i - T1;
        if (j < H2 * N1) {
            int n = j / N1, k = j - n * N1;
            g_w2t[j] = __uint_as_float(tf32b(W2[k * H2 + n]));
        }
    }
}

__global__ void zero_pool_kernel() {
    int i = blockIdx.x * blockDim.x + threadIdx.x;
    if (i < NG * H2) g_pool[i] = 0.0f;
}

// -------- fused MLP + pool --------
extern __shared__ char sm[];

__global__ __launch_bounds__(NTH) void mlp_kernel(
    const float* __restrict__ h, const float* __restrict__ x,
    const int* __restrict__ batch,
    const float* __restrict__ b1, const float* __restrict__ b2, int N)
{
    const int t = threadIdx.x;
    const int wid = t >> 5, lane = t & 31;
    const int q4 = lane & 3, rr = lane >> 2;
    const int node0 = blockIdx.x * TM;
    const int valid = min(TM, N - node0);
    const uint32_t smb = smem_u32(sm);
    float* b1s = (float*)(sm + OFF_B1);
    float* b2s = (float*)(sm + OFF_B2);
    float* z2s = (float*)(sm + OFF_Z2);

    // ---- persistent staging: W2 (swizzled wide layout), biases ----
    #pragma unroll
    for (int r = 0; r < 8; r++) {
        int i = t + NTH * r;                     // 0..4095 float4s
        int n = i >> 6, q = i & 63;              // k = 4q
        float4 v = *(const float4*)&g_w2t[n * N1 + q * 4];
        *(float4*)(sm + OFF_W2 + adrW(n, q * 4)) = v;
    }
    if (t < N1) b1s[t] = b1[t];
    if (t < H2) b2s[t] = b2[t];

    // ---- GEMM1: [128 x 416] x [416 x 256] ----
    const int wr = wid >> 3, wc = wid & 7;       // warp grid 2 x 8
    const int m0w = wr * 64, n0w = wc * 32;      // warp tile 64 x 32
    float acc[4][4][4];
    #pragma unroll
    for (int a = 0; a < 4; a++)
        #pragma unroll
        for (int b = 0; b < 4; b++)
            #pragma unroll
            for (int c = 0; c < 4; c++) acc[a][b][c] = 0.0f;

    // A LDG helper values (2 float4 per thread per chunk)
    float4 pre0, pre1;
    int am0, aq0, am1, aq1;
    {
        int i0 = t;             am0 = i0 >> 3; aq0 = i0 & 7;
        int i1 = t + NTH;       am1 = i1 >> 3; aq1 = i1 & 7;
    }

    #define LDG_A(cc, v, m, q) do {                                           \
        int k = (cc) * 32 + (q) * 4;                                          \
        v = make_float4(0.f, 0.f, 0.f, 0.f);                                  \
        if ((m) < valid && k < DIN) {                                         \
            size_t node = (size_t)(node0 + (m));                              \
            v = (k < HID) ? *(const float4*)(h + node * HID + k)              \
                          : *(const float4*)(x + node * HID + (k - HID));     \
        } } while (0)

    #define STS_A(cc, v, m, q) do {                                           \
        uint32_t o = OFF_A + ((cc) % 3) * 16384 + adrC(m, (q) * 4);           \
        uint4 u = make_uint4(tf32b(v.x), tf32b(v.y), tf32b(v.z), tf32b(v.w)); \
        *(uint4*)(sm + o) = u; } while (0)

    #define STAGE_B(cc) do {                                                  \
        uint32_t base = smb + OFF_BB + ((cc) % 3) * 32768;                    \
        _Pragma("unroll")                                                     \
        for (int r = 0; r < 4; r++) {                                         \
            int i = t + NTH * r;                                              \
            int n = i >> 3, q = i & 7;                                        \
            cp16(base + adrC(n, q * 4), g_w1t + n * KPAD + (cc) * 32 + q * 4);\
        } } while (0)

    // prologue: chunk 0
    LDG_A(0, pre0, am0, aq0); LDG_A(0, pre1, am1, aq1);
    STAGE_B(0); CP_COMMIT;
    STS_A(0, pre0, am0, aq0); STS_A(0, pre1, am1, aq1);

    for (int c = 0; c < NCHUNK; c++) {
        float4 nx0, nx1;
        if (c + 1 < NCHUNK) {
            LDG_A(c + 1, nx0, am0, aq0); LDG_A(c + 1, nx1, am1, aq1);
            STAGE_B(c + 1); CP_COMMIT;
            CP_WAIT1;
        } else {
            CP_WAIT0;
        }
        __syncthreads();    // A(c)+B(c) visible; prior reads of buf (c+1)%3 done

        const char* bA = sm + OFF_A  + (c % 3) * 16384;
        const char* bB = sm + OFF_BB + (c % 3) * 32768;
        #pragma unroll
        for (int ks = 0; ks < 4; ks++) {
            const int kq = ks * 8 + q4;
            uint32_t a[4][4], b[4][2];
            #pragma unroll
            for (int mf = 0; mf < 4; mf++) {
                int r = m0w + mf * 16 + rr;
                a[mf][0] = *(const uint32_t*)(bA + adrC(r,     kq));
                a[mf][1] = *(const uint32_t*)(bA + adrC(r + 8, kq));
                a[mf][2] = *(const uint32_t*)(bA + adrC(r,     kq + 4));
                a[mf][3] = *(const uint32_t*)(bA + adrC(r + 8, kq + 4));
            }
            #pragma unroll
            for (int nf = 0; nf < 4; nf++) {
                int n = n0w + nf * 8 + rr;
                b[nf][0] = *(const uint32_t*)(bB + adrC(n, kq));
                b[nf][1] = *(const uint32_t*)(bB + adrC(n, kq + 4));
            }
            #pragma unroll
            for (int mf = 0; mf < 4; mf++)
                #pragma unroll
                for (int nf = 0; nf < 4; nf++)
                    mma_tf32(acc[mf][nf], a[mf][0], a[mf][1], a[mf][2], a[mf][3], b[nf][0], b[nf][1]);
        }
        if (c + 1 < NCHUNK) { STS_A(c + 1, nx0, am0, aq0); STS_A(c + 1, nx1, am1, aq1); }
    }
    __syncthreads();    // all GEMM1 reads done before z1 overwrites buffers

    // ---- epilogue1: z1 = tf32(relu(acc + b1)) -> SMEM wide layout ----
    #pragma unroll
    for (int mf = 0; mf < 4; mf++) {
        #pragma unroll
        for (int nf = 0; nf < 4; nf++) {
            int col = n0w + nf * 8 + 2 * q4;
            int r   = m0w + mf * 16 + rr;
            float v0 = fmaxf(acc[mf][nf][0] + b1s[col],     0.0f);
            float v1 = fmaxf(acc[mf][nf][1] + b1s[col + 1], 0.0f);
            float v2 = fmaxf(acc[mf][nf][2] + b1s[col],     0.0f);
            float v3 = fmaxf(acc[mf][nf][3] + b1s[col + 1], 0.0f);
            *(uint2*)(sm + OFF_Z1 + adrW(r,     col)) = make_uint2(tf32b(v0), tf32b(v1));
            *(uint2*)(sm + OFF_Z1 + adrW(r + 8, col)) = make_uint2(tf32b(v2), tf32b(v3));
        }
    }
    __syncthreads();

    // ---- GEMM2: [128 x 256] x [256 x 64], warp tile 16 x 32 ----
    const int m02 = (wid >> 1) * 16;
    const int n02 = (wid & 1) * 32;
    float ac2[4][4];
    #pragma unroll
    for (int a = 0; a < 4; a++)
        #pragma unroll
        for (int b = 0; b < 4; b++) ac2[a][b] = 0.0f;

    #pragma unroll 8
    for (int ks = 0; ks < 32; ks++) {
        const int kq = ks * 8 + q4;
        int r = m02 + rr;
        uint32_t a0 = *(const uint32_t*)(sm + OFF_Z1 + adrW(r,     kq));
        uint32_t a1 = *(const uint32_t*)(sm + OFF_Z1 + adrW(r + 8, kq));
        uint32_t a2 = *(const uint32_t*)(sm + OFF_Z1 + adrW(r,     kq + 4));
        uint32_t a3 = *(const uint32_t*)(sm + OFF_Z1 + adrW(r + 8, kq + 4));
        #pragma unroll
        for (int nf = 0; nf < 4; nf++) {
            int n = n02 + nf * 8 + rr;
            uint32_t b0 = *(const uint32_t*)(sm + OFF_W2 + adrW(n, kq));
            uint32_t b1r = *(const uint32_t*)(sm + OFF_W2 + adrW(n, kq + 4));
            mma_tf32(ac2[nf], a0, a1, a2, a3, b0, b1r);
        }
    }
    __syncthreads();    // all GEMM2 reads of z1 done before z2 overwrites

    // ---- epilogue2: z2 = relu(ac2 + b2) -> SMEM [m][68] ----
    #pragma unroll
    for (int nf = 0; nf < 4; nf++) {
        int col = n02 + nf * 8 + 2 * q4;
        int r   = m02 + rr;
        z2s[r * 68 + col]           = fmaxf(ac2[nf][0] + b2s[col],     0.0f);
        z2s[r * 68 + col + 1]       = fmaxf(ac2[nf][1] + b2s[col + 1], 0.0f);
        z2s[(r + 8) * 68 + col]     = fmaxf(ac2[nf][2] + b2s[col],     0.0f);
        z2s[(r + 8) * 68 + col + 1] = fmaxf(ac2[nf][3] + b2s[col + 1], 0.0f);
    }
    __syncthreads();

    // ---- pooling: run-merged segment atomics (batch sorted) ----
    {
        const int cc = t & 63, grp = t >> 6;     // 8 groups x 16 rows
        const int mstart = grp * 16;
        if (mstart < valid) {
            const int mend = min(mstart + 16, valid);
            int cur = batch[node0 + mstart];
            float sum = z2s[mstart * 68 + cc];
            for (int m = mstart + 1; m < mend; m++) {
                int g = batch[node0 + m];
                float v = z2s[m * 68 + cc];
                if (g == cur) sum += v;
                else { atomicAdd(&g_pool[cur * H2 + cc], sum); cur = g; sum = v; }
            }
            atomicAdd(&g_pool[cur * H2 + cc], sum);
        }
    }
}

// -------- readout --------
__global__ void out_kernel(const float* __restrict__ Wout,
                           const float* __restrict__ bout,
                           float* __restrict__ out)
{
    int gw = (blockIdx.x * blockDim.x + threadIdx.x) >> 5;
    int lane = threadIdx.x & 31;
    if (gw >= NG) return;
    float a = g_pool[gw * H2 + lane]      * Wout[lane]
            + g_pool[gw * H2 + 32 + lane] * Wout[32 + lane];
    #pragma unroll
    for (int o = 16; o; o >>= 1) a += __shfl_xor_sync(0xffffffffu, a, o);
    if (lane == 0) out[gw] = 1.0f / (1.0f + expf(-(a + bout[0])));
}

extern "C" void kernel_launch(void* const* d_in, const int* in_sizes, int n_in,
                              void* d_out, int out_size)
{
    const float* h    = (const float*)d_in[0];
    const float* x    = (const float*)d_in[1];
    const int*   batch= (const int*)  d_in[2];
    const float* W1   = (const float*)d_in[3];
    const float* b1   = (const float*)d_in[4];
    const float* W2   = (const float*)d_in[5];
    const float* b2   = (const float*)d_in[6];
    const float* Wout = (const float*)d_in[7];
    const float* bout = (const float*)d_in[8];
    float* out = (float*)d_out;

    const int N = in_sizes[2];
    const int prep_total = N1 * KPAD + H2 * N1;

    cudaFuncSetAttribute(mlp_kernel, cudaFuncAttributeMaxDynamicSharedMemorySize, SMEM_BYTES);

    prep_kernel<<<(prep_total + 255) / 256, 256>>>(W1, W2);
    zero_pool_kernel<<<(NG * H2 + 255) / 256, 256>>>();
    mlp_kernel<<<(N + TM - 1) / TM, NTH, SMEM_BYTES>>>(h, x, batch, b1, b2, N);
    out_kernel<<<(NG * 32 + 255) / 256, 256>>>(Wout, bout, out);
}